// round 14
// baseline (speedup 1.0000x reference)
#include <cuda_runtime.h>

// Problem dims
#define N_   32
#define C_   256
#define H_   56
#define W_   56
#define HW_  (H_ * W_)          // 3136
#define NP_  (N_ * HW_)         // 100352 pixels
#define QUADS (NP_ / 4)         // 25088
#define OCTS  (NP_ / 8)         // 12544
#define KW_CAP 2304

#define G_       444            // grid size == 148 SMs * 3 blocks (co-resident)
#define CCHUNKS  8              // csum channel chunks (32 ch each)
#define CPER     (C_ / CCHUNKS) // 32
#define OCHUNK   4              // channels per k_out unit thread
#define CS_UNITS (CCHUNKS * 49) // 392 csum units (256 octs each)
#define WS_BLOCKS (G_ - CS_UNITS) // 52 wscan blocks
#define BOX_UNITS (QUADS / 256) // 98 box units (256 quads each)
#define OUT_UNITS (49 * (C_ / OCHUNK)) // 3136 k_out units

// ---------------- scratch (static device; no resets needed) -----------------
__device__ float  g_sum[NP_];            // accumulated channel sum (zeroed each run by phase 4)
__device__ float  g_S[NP_];              // 3x3 box sum
__device__ double g_p1[BOX_UNITS], g_p2[BOX_UNITS];
__device__ int    g_devList[C_ * KW_CAP];
__device__ int    g_devCnt[C_];
__device__ int    g_anyDev;
__device__ float  g_a[C_], g_b[C_];
// grid barrier state: count self-resets; sense persists (sense-reversal)
__device__ unsigned g_count = 0;
__device__ volatile unsigned g_sense = 0;

__device__ __forceinline__ float sgn(float v) {
    return (float)((v > 0.0f) - (v < 0.0f));
}

// ---- 256-bit L2-policy accesses (evict hints require .v8.b32 on sm_103a) ----
__device__ __forceinline__ void ldg_evict_last8(const float* p, float* v) {
    asm volatile("ld.global.nc.L2::evict_last.v8.b32 {%0,%1,%2,%3,%4,%5,%6,%7}, [%8];"
                 : "=f"(v[0]), "=f"(v[1]), "=f"(v[2]), "=f"(v[3]),
                   "=f"(v[4]), "=f"(v[5]), "=f"(v[6]), "=f"(v[7]) : "l"(p));
}
__device__ __forceinline__ void ldg_evict_first8(const float* p, float* v) {
    asm volatile("ld.global.nc.L2::evict_first.v8.b32 {%0,%1,%2,%3,%4,%5,%6,%7}, [%8];"
                 : "=f"(v[0]), "=f"(v[1]), "=f"(v[2]), "=f"(v[3]),
                   "=f"(v[4]), "=f"(v[5]), "=f"(v[6]), "=f"(v[7]) : "l"(p));
}
__device__ __forceinline__ void stg_evict_first8(float* p, const float* v) {
    asm volatile("st.global.L2::evict_first.v8.b32 [%0], {%1,%2,%3,%4,%5,%6,%7,%8};"
                 :: "l"(p), "f"(v[0]), "f"(v[1]), "f"(v[2]), "f"(v[3]),
                    "f"(v[4]), "f"(v[5]), "f"(v[6]), "f"(v[7]) : "memory");
}
__device__ __forceinline__ void red_add_v4(float* p, const float* v) {
    asm volatile("red.global.add.v4.f32 [%0], {%1,%2,%3,%4};"
                 :: "l"(p), "f"(v[0]), "f"(v[1]), "f"(v[2]), "f"(v[3]) : "memory");
}

// ---- software grid barrier (all G_ blocks co-resident by construction) ----
__device__ __forceinline__ void gbar(unsigned& ls) {
    unsigned target = ls ^ 1u;
    ls = target;
    __threadfence();                      // release this block's writes
    __syncthreads();
    if (threadIdx.x == 0) {
        if (atomicAdd(&g_count, 1u) == G_ - 1u) {
            g_count = 0;                  // self-reset for next barrier/replay
            __threadfence();
            g_sense = target;             // release
        } else {
            while (g_sense != target) { __nanosleep(64); }
            __threadfence();              // acquire
        }
    }
    __syncthreads();
}

__device__ __forceinline__ float signx_at(const float* __restrict__ x,
                                          int n, int c, int hh, int ww) {
    if (hh < 0 || hh >= H_ || ww < 0 || ww >= W_) return 0.0f;
    float v = x[((size_t)n * C_ + c) * HW_ + hh * W_ + ww];
    return sgn(v);
}

// ---------------- ONE persistent kernel, four phases -------------------------
__global__ void __launch_bounds__(256, 3) k_fused(const float* __restrict__ x,
                                                  const float* __restrict__ w,
                                                  const float* __restrict__ gamma,
                                                  const float* __restrict__ beta,
                                                  float* __restrict__ out) {
    __shared__ double sh[512];            // 4KB, reused across phases
    __shared__ int shi[2];                // [0]=wscan cnt, [1]=anyDev
    unsigned ls = g_sense;                // volatile read; stable at launch
    int b = blockIdx.x, tid = threadIdx.x;

    // ===== phase 1: csum (blocks 0..391) + wscan (blocks 392..443) =====
    if (b < CS_UNITS) {
        int pl = b / 49, blk = b - pl * 49;
        int q  = blk * 256 + tid;              // oct index
        int p8 = q * 8;
        int n  = p8 / HW_;
        int hw = p8 - n * HW_;
        const float* xp = x + ((size_t)n * C_ + pl * CPER) * HW_ + hw;
        float acc[8] = {0.f, 0.f, 0.f, 0.f, 0.f, 0.f, 0.f, 0.f};
#pragma unroll
        for (int c = 0; c < CPER; c++) {
            float v[8];
            ldg_evict_last8(xp + (size_t)c * HW_, v);   // keep x L2-resident
#pragma unroll
            for (int l = 0; l < 8; l++) acc[l] += sgn(v[l]);
        }
        red_add_v4(g_sum + p8,     acc);
        red_add_v4(g_sum + p8 + 4, acc + 4);
    } else {
        int e = b - CS_UNITS;                  // 0..51
        for (int o = e; o < C_; o += WS_BLOCKS) {
            if (tid == 0) shi[0] = 0;
            __syncthreads();
            const float* wo = w + (size_t)o * (C_ * 9);
#pragma unroll
            for (int j = 0; j < 9; j++) {
                int i = tid * 9 + j;           // i < 2304
                float v = wo[i];
                int s = (v > 0.0f) - (v < 0.0f);
                int delta = s - 1;
                if (delta != 0) {
                    int c = i / 9, k = i - c * 9;
                    int slot = atomicAdd(&shi[0], 1);
                    g_devList[o * KW_CAP + slot] = (c << 6) | (k << 2) | (delta + 2);
                }
            }
            __syncthreads();
            if (tid == 0) g_devCnt[o] = shi[0];
            __syncthreads();
        }
    }
    gbar(ls);

    // ===== phase 2: 3x3 box + stats partials (blocks 0..97) =====
    if (b < BOX_UNITS) {
        int q  = b * 256 + tid;                // quad index
        int p4 = q * 4;
        int n  = p4 / HW_;
        int hw = p4 - n * HW_;
        int h  = hw / W_, w0 = hw - h * W_;    // w0 % 4 == 0

        float v0 = 0.f, v1 = 0.f, v2 = 0.f, v3 = 0.f, v4 = 0.f, v5 = 0.f;
        const float* base = g_sum + n * HW_;
#pragma unroll
        for (int dh = -1; dh <= 1; dh++) {
            int hh = h + dh;
            if ((unsigned)hh < (unsigned)H_) {
                const float* r = base + hh * W_;
                if (w0 > 0)       v0 += r[w0 - 1];
                float4 m = *reinterpret_cast<const float4*>(r + w0);
                v1 += m.x; v2 += m.y; v3 += m.z; v4 += m.w;
                if (w0 + 4 < W_)  v5 += r[w0 + 4];
            }
        }
        float S0 = v0 + v1 + v2;
        float S1 = v1 + v2 + v3;
        float S2 = v2 + v3 + v4;
        float S3 = v3 + v4 + v5;
        float4 o4; o4.x = S0; o4.y = S1; o4.z = S2; o4.w = S3;
        *reinterpret_cast<float4*>(g_S + p4) = o4;

        double s1 = (double)S0 + (double)S1 + (double)S2 + (double)S3;
        double s2 = (double)S0*S0 + (double)S1*S1 + (double)S2*S2 + (double)S3*S3;
#pragma unroll
        for (int off = 16; off > 0; off >>= 1) {
            s1 += __shfl_xor_sync(0xffffffffu, s1, off);
            s2 += __shfl_xor_sync(0xffffffffu, s2, off);
        }
        int lane = tid & 31, warp = tid >> 5;
        if (lane == 0) { sh[warp] = s1; sh[8 + warp] = s2; }
        __syncthreads();
        if (tid == 0) {
            double a1 = 0.0, a2 = 0.0;
#pragma unroll
            for (int i = 0; i < 8; i++) { a1 += sh[i]; a2 += sh[8 + i]; }
            g_p1[b] = a1; g_p2[b] = a2;
        }
    }
    gbar(ls);

    // ===== phase 3: BN params (block 0 only) =====
    if (b == 0) {
        // reduce 98 partials
        sh[tid]       = (tid < BOX_UNITS) ? g_p1[tid] : 0.0;
        sh[256 + tid] = (tid < BOX_UNITS) ? g_p2[tid] : 0.0;
        __syncthreads();
#pragma unroll
        for (int off = 128; off > 0; off >>= 1) {
            if (tid < off) { sh[tid] += sh[tid + off]; sh[256 + tid] += sh[256 + tid + off]; }
            __syncthreads();
        }
        double baseSum = sh[0], baseSum2 = sh[256];

        if (tid == 0) shi[1] = 0;
        __syncthreads();
        if (tid < 128) {
            if (g_devCnt[tid] != 0 || g_devCnt[tid + 128] != 0) atomicAdd(&shi[1], 1);
        }
        __syncthreads();
        if (tid == 0) g_anyDev = shi[1];

        // one channel per thread
        int c = tid;
        double c1 = 0.0, c2 = 0.0, c3 = 0.0;
        int cnt = g_devCnt[c];
        if (cnt != 0) {                        // never-taken serial fallback
            const int* list = g_devList + c * KW_CAP;
            for (int p = 0; p < NP_; p++) {
                int nn = p / HW_;
                int phw = p - nn * HW_;
                int ph = phw / W_, pw = phw - (phw / W_) * W_;
                float corr = 0.0f;
                for (int j = 0; j < cnt; j++) {
                    int e = list[j];
                    int cin = e >> 6;
                    int k   = (e >> 2) & 15;
                    float delta = (float)((e & 3) - 2);
                    corr += delta * signx_at(x, nn, cin, ph + k / 3 - 1, pw + k % 3 - 1);
                }
                c1 += (double)corr;
                c2 += (double)g_S[p] * (double)corr;
                c3 += (double)corr * (double)corr;
            }
        }
        const double M = (double)NP_;
        double mean = (baseSum + c1) / M;
        double ex2  = (baseSum2 + 2.0 * c2 + c3) / M;
        double var  = ex2 - mean * mean;
        float a = gamma[c] * (float)(1.0 / sqrt(var + 1e-5));
        g_a[c] = a;
        g_b[c] = beta[c] - a * (float)mean;
    }
    gbar(ls);

    // ===== phase 4: normalize + residual (3136 units, work-looped) =====
    int anyDev = g_anyDev;
    for (int u = b; u < OUT_UNITS; u += G_) {
        int cy   = u / 49;
        int blkx = u - cy * 49;
        int q  = blkx * 256 + tid;             // oct index
        int c0 = cy * OCHUNK;
        int p8 = q * 8;
        int n  = p8 / HW_;
        int hw = p8 - n * HW_;

        if (cy == 0) {                         // reset accumulator plane
            float4 z; z.x = 0.f; z.y = 0.f; z.z = 0.f; z.w = 0.f;
            *reinterpret_cast<float4*>(g_sum + p8)     = z;
            *reinterpret_cast<float4*>(g_sum + p8 + 4) = z;
        }

        float Ss[8];
        *reinterpret_cast<float4*>(Ss)     = *reinterpret_cast<const float4*>(g_S + p8);
        *reinterpret_cast<float4*>(Ss + 4) = *reinterpret_cast<const float4*>(g_S + p8 + 4);
        size_t base = ((size_t)n * C_ + c0) * HW_ + hw;

        if (anyDev == 0) {
            float xs[OCHUNK][8];
#pragma unroll
            for (int cc = 0; cc < OCHUNK; cc++)
                ldg_evict_first8(x + base + (size_t)cc * HW_, xs[cc]);
            float av[OCHUNK], bv[OCHUNK];
#pragma unroll
            for (int cc = 0; cc < OCHUNK; cc++) { av[cc] = g_a[c0 + cc]; bv[cc] = g_b[c0 + cc]; }
#pragma unroll
            for (int cc = 0; cc < OCHUNK; cc++) {
                float a = av[cc], bb = bv[cc];
                float o8[8];
#pragma unroll
                for (int l = 0; l < 8; l++)
                    o8[l] = fmaf(a, Ss[l], bb) + xs[cc][l];
                stg_evict_first8(out + base + (size_t)cc * HW_, o8);
            }
            continue;
        }

        // slow path (weight deviants exist)
        for (int cc = 0; cc < OCHUNK; cc++) {
            int c = c0 + cc;
            float a = g_a[c], bb = g_b[c];
            float Sc[8];
#pragma unroll
            for (int l = 0; l < 8; l++) Sc[l] = Ss[l];
            int cnt = g_devCnt[c];
            if (cnt != 0) {
                const int* list = g_devList + c * KW_CAP;
                int h = hw / W_, w0 = hw - (hw / W_) * W_;
                for (int j = 0; j < cnt; j++) {
                    int e = list[j];
                    int cin = e >> 6;
                    int k   = (e >> 2) & 15;
                    float delta = (float)((e & 3) - 2);
                    int dh = k / 3 - 1, dw = k % 3 - 1;
#pragma unroll
                    for (int l = 0; l < 8; l++)
                        Sc[l] += delta * signx_at(x, n, cin, h + dh, w0 + l + dw);
                }
            }
            size_t idx = base + (size_t)cc * HW_;
#pragma unroll
            for (int l = 0; l < 8; l++)
                out[idx + l] = fmaf(a, Sc[l], bb) + x[idx + l];
        }
    }
}

// ---------------- launch -----------------------------------------------------
extern "C" void kernel_launch(void* const* d_in, const int* in_sizes, int n_in,
                              void* d_out, int out_size) {
    const float* x     = (const float*)d_in[0];
    const float* w     = (const float*)d_in[1];
    const float* gamma = (const float*)d_in[2];
    const float* beta  = (const float*)d_in[3];
    float* out = (float*)d_out;

    k_fused<<<G_, 256>>>(x, w, gamma, beta, out);
}

// round 17
// speedup vs baseline: 1.0355x; 1.0355x over previous
#include <cuda_runtime.h>

// Problem dims
#define N_   32
#define C_   256
#define H_   56
#define W_   56
#define HW_  (H_ * W_)          // 3136
#define NP_  (N_ * HW_)         // 100352 pixels
#define QUADS (NP_ / 4)         // 25088
#define OCTS  (NP_ / 8)         // 12544
#define KW_CAP 2304

#define CCHUNKS 8               // csum channel chunks (32 ch each)
#define CPER    (C_ / CCHUNKS)  // 32
#define OCHUNK  4               // channels per thread in k_out
#define CS_UNITS (CCHUNKS * 49) // 392 csum blocks
#define FRONT_G  (CS_UNITS + C_) // 648: csum + 256 wscan blocks
#define BOX_UNITS (QUADS / 256) // 98 box units (256 quads each)
#define OUT_BLOCKS (OCTS / 256) // 49

// ---------------- scratch (static device) -----------------------------------
__device__ float  g_sum[NP_];            // zero-init; k_out re-zeroes each run
__device__ float  g_S[NP_];              // 3x3 box sum
__device__ double g_p1[BOX_UNITS], g_p2[BOX_UNITS];
__device__ int    g_devList[C_ * KW_CAP];
__device__ int    g_devCnt[C_];
__device__ int    g_anyDev;
__device__ float  g_a[C_], g_b[C_];
__device__ unsigned g_done = 0;          // phase-1 completion counter (self-reset)
__device__ unsigned g_ticket = 0;        // last-box-block election (self-reset)

__device__ __forceinline__ float sgn(float v) {
    return (float)((v > 0.0f) - (v < 0.0f));
}

// ---- 256-bit L2-policy accesses (evict hints require .v8.b32 on sm_103a) ----
__device__ __forceinline__ void ldg_evict_last8(const float* p, float* v) {
    asm volatile("ld.global.nc.L2::evict_last.v8.b32 {%0,%1,%2,%3,%4,%5,%6,%7}, [%8];"
                 : "=f"(v[0]), "=f"(v[1]), "=f"(v[2]), "=f"(v[3]),
                   "=f"(v[4]), "=f"(v[5]), "=f"(v[6]), "=f"(v[7]) : "l"(p));
}
__device__ __forceinline__ void ldg_evict_first8(const float* p, float* v) {
    asm volatile("ld.global.nc.L2::evict_first.v8.b32 {%0,%1,%2,%3,%4,%5,%6,%7}, [%8];"
                 : "=f"(v[0]), "=f"(v[1]), "=f"(v[2]), "=f"(v[3]),
                   "=f"(v[4]), "=f"(v[5]), "=f"(v[6]), "=f"(v[7]) : "l"(p));
}
__device__ __forceinline__ void stg_evict_first8(float* p, const float* v) {
    asm volatile("st.global.L2::evict_first.v8.b32 [%0], {%1,%2,%3,%4,%5,%6,%7,%8};"
                 :: "l"(p), "f"(v[0]), "f"(v[1]), "f"(v[2]), "f"(v[3]),
                    "f"(v[4]), "f"(v[5]), "f"(v[6]), "f"(v[7]) : "memory");
}
__device__ __forceinline__ void red_add_v4(float* p, const float* v) {
    asm volatile("red.global.add.v4.f32 [%0], {%1,%2,%3,%4};"
                 :: "l"(p), "f"(v[0]), "f"(v[1]), "f"(v[2]), "f"(v[3]) : "memory");
}

__device__ __forceinline__ float signx_at(const float* __restrict__ x,
                                          int n, int c, int hh, int ww) {
    if (hh < 0 || hh >= H_ || ww < 0 || ww >= W_) return 0.0f;
    float v = x[((size_t)n * C_ + c) * HW_ + hh * W_ + ww];
    return sgn(v);
}

// ---------------- kernel 1: csum + wscan + box + params (front) --------------
__global__ void __launch_bounds__(256) k_front(const float* __restrict__ x,
                                               const float* __restrict__ w,
                                               const float* __restrict__ gamma,
                                               const float* __restrict__ beta) {
    int b = blockIdx.x, tid = threadIdx.x;
    __shared__ int shcnt;

    // ===== phase 1 =====
    if (b < CS_UNITS) {
        int pl = b / 49, blk = b - pl * 49;
        int q  = blk * 256 + tid;              // oct index
        int p8 = q * 8;
        int n  = p8 / HW_;
        int hw = p8 - n * HW_;
        const float* xp = x + ((size_t)n * C_ + pl * CPER) * HW_ + hw;
        float acc[8] = {0.f, 0.f, 0.f, 0.f, 0.f, 0.f, 0.f, 0.f};
#pragma unroll
        for (int c = 0; c < CPER; c++) {
            float v[8];
            ldg_evict_last8(xp + (size_t)c * HW_, v);   // keep x L2-resident
#pragma unroll
            for (int l = 0; l < 8; l++) acc[l] += sgn(v[l]);
        }
        red_add_v4(g_sum + p8,     acc);
        red_add_v4(g_sum + p8 + 4, acc + 4);
    } else {
        int o = b - CS_UNITS;                  // one channel per block
        if (tid == 0) shcnt = 0;
        __syncthreads();
        const float* wo = w + (size_t)o * (C_ * 9);
#pragma unroll
        for (int j = 0; j < 9; j++) {
            int i = tid * 9 + j;               // i < 2304
            float v = wo[i];
            int s = (v > 0.0f) - (v < 0.0f);
            int delta = s - 1;
            if (delta != 0) {
                int c = i / 9, k = i - c * 9;
                int slot = atomicAdd(&shcnt, 1);
                g_devList[o * KW_CAP + slot] = (c << 6) | (k << 2) | (delta + 2);
            }
        }
        __syncthreads();
        if (tid == 0) g_devCnt[o] = shcnt;
    }

    // ----- RELEASE: per-warp fence FIRST, barrier, THEN signal -----
    __threadfence();                           // each warp orders its own REDs/stores
    __syncthreads();                           // all warps' fences have executed
    if (tid == 0) atomicAdd(&g_done, 1u);      // publish
    if (b >= BOX_UNITS) return;                // 550 blocks exit here

    // ----- ACQUIRE: spin, barrier, fence -----
    if (tid == 0) {
        while (atomicAdd(&g_done, 0u) < FRONT_G) { __nanosleep(64); }
    }
    __syncthreads();
    __threadfence();

    // ===== phase 2: box unit b (256 quads, 8 warps) =====
    {
        int q  = b * 256 + tid;                // quad index (98*256 = QUADS)
        int p4 = q * 4;
        int n  = p4 / HW_;
        int hw = p4 - n * HW_;
        int h  = hw / W_, w0 = hw - h * W_;    // w0 % 4 == 0

        float v0 = 0.f, v1 = 0.f, v2 = 0.f, v3 = 0.f, v4 = 0.f, v5 = 0.f;
        const float* base = g_sum + n * HW_;
#pragma unroll
        for (int dh = -1; dh <= 1; dh++) {
            int hh = h + dh;
            if ((unsigned)hh < (unsigned)H_) {
                const float* r = base + hh * W_;
                if (w0 > 0)       v0 += r[w0 - 1];
                float4 m = *reinterpret_cast<const float4*>(r + w0);
                v1 += m.x; v2 += m.y; v3 += m.z; v4 += m.w;
                if (w0 + 4 < W_)  v5 += r[w0 + 4];
            }
        }
        float S0 = v0 + v1 + v2;
        float S1 = v1 + v2 + v3;
        float S2 = v2 + v3 + v4;
        float S3 = v3 + v4 + v5;
        float4 o4; o4.x = S0; o4.y = S1; o4.z = S2; o4.w = S3;
        *reinterpret_cast<float4*>(g_S + p4) = o4;

        double s1 = (double)S0 + (double)S1 + (double)S2 + (double)S3;
        double s2 = (double)S0*S0 + (double)S1*S1 + (double)S2*S2 + (double)S3*S3;
#pragma unroll
        for (int off = 16; off > 0; off >>= 1) {
            s1 += __shfl_xor_sync(0xffffffffu, s1, off);
            s2 += __shfl_xor_sync(0xffffffffu, s2, off);
        }
        // R15/R16 BUG FIX: 256 threads = 8 warps -> arrays must hold 8 partials
        __shared__ double w1[8], w2[8];
        int lane = tid & 31, warp = tid >> 5;
        if (lane == 0) { w1[warp] = s1; w2[warp] = s2; }
        __threadfence();                       // order g_S stores before ticket
        __syncthreads();
        __shared__ bool isLast;
        if (tid == 0) {
            double a1 = 0.0, a2 = 0.0;
#pragma unroll
            for (int i = 0; i < 8; i++) { a1 += w1[i]; a2 += w2[i]; }
            g_p1[b] = a1;
            g_p2[b] = a2;
            __threadfence();
            unsigned t = atomicAdd(&g_ticket, 1u);
            isLast = (t == BOX_UNITS - 1);
            if (isLast) { g_ticket = 0; g_done = 0; }   // self-reset for replay
        }
        __syncthreads();
        if (!isLast) return;
    }

    // ===== phase 3 (last box block): reduce partials, BN params =====
    {
        __threadfence();                       // acquire g_p1/g_p2
        __shared__ double r1[256], r2[256];
        r1[tid] = (tid < BOX_UNITS) ? g_p1[tid] : 0.0;
        r2[tid] = (tid < BOX_UNITS) ? g_p2[tid] : 0.0;
        __syncthreads();
#pragma unroll
        for (int off = 128; off > 0; off >>= 1) {
            if (tid < off) { r1[tid] += r1[tid + off]; r2[tid] += r2[tid + off]; }
            __syncthreads();
        }
        double baseSum = r1[0], baseSum2 = r2[0];

        __shared__ int anyDev;
        if (tid == 0) anyDev = 0;
        __syncthreads();
        if (tid < 128) {
            if (g_devCnt[tid] != 0 || g_devCnt[tid + 128] != 0) atomicAdd(&anyDev, 1);
        }
        __syncthreads();
        if (tid == 0) g_anyDev = anyDev;

        int c = tid;                            // one channel per thread
        double c1 = 0.0, c2 = 0.0, c3 = 0.0;
        int cnt = g_devCnt[c];
        if (cnt != 0) {                         // never-taken serial fallback
            const int* list = g_devList + c * KW_CAP;
            for (int p = 0; p < NP_; p++) {
                int nn = p / HW_;
                int phw = p - nn * HW_;
                int ph = phw / W_, pw = phw - (phw / W_) * W_;
                float corr = 0.0f;
                for (int j = 0; j < cnt; j++) {
                    int e = list[j];
                    int cin = e >> 6;
                    int k   = (e >> 2) & 15;
                    float delta = (float)((e & 3) - 2);
                    corr += delta * signx_at(x, nn, cin, ph + k / 3 - 1, pw + k % 3 - 1);
                }
                c1 += (double)corr;
                c2 += (double)g_S[p] * (double)corr;
                c3 += (double)corr * (double)corr;
            }
        }
        const double M = (double)NP_;
        double mean = (baseSum + c1) / M;
        double ex2  = (baseSum2 + 2.0 * c2 + c3) / M;
        double var  = ex2 - mean * mean;
        float a = gamma[c] * (float)(1.0 / sqrt(var + 1e-5));
        g_a[c] = a;
        g_b[c] = beta[c] - a * (float)mean;
    }
}

// ---------------- kernel 2: normalize + residual (unchanged from R13) -------
__global__ void __launch_bounds__(256) k_out(const float* __restrict__ x,
                                             float* __restrict__ out) {
    int q = blockIdx.x * 256 + threadIdx.x;      // oct index, exact grid
    int c0 = blockIdx.y * OCHUNK;
    int p8 = q * 8;
    int n  = p8 / HW_;
    int hw = p8 - n * HW_;

    if (blockIdx.y == 0) {                       // reset accumulator plane
        float4 z; z.x = 0.f; z.y = 0.f; z.z = 0.f; z.w = 0.f;
        *reinterpret_cast<float4*>(g_sum + p8)     = z;
        *reinterpret_cast<float4*>(g_sum + p8 + 4) = z;
    }

    float Ss[8];
    *reinterpret_cast<float4*>(Ss)     = *reinterpret_cast<const float4*>(g_S + p8);
    *reinterpret_cast<float4*>(Ss + 4) = *reinterpret_cast<const float4*>(g_S + p8 + 4);
    size_t base = ((size_t)n * C_ + c0) * HW_ + hw;

    if (g_anyDev == 0) {
        float xs[OCHUNK][8];
#pragma unroll
        for (int cc = 0; cc < OCHUNK; cc++)
            ldg_evict_first8(x + base + (size_t)cc * HW_, xs[cc]);
        float av[OCHUNK], bv[OCHUNK];
#pragma unroll
        for (int cc = 0; cc < OCHUNK; cc++) { av[cc] = g_a[c0 + cc]; bv[cc] = g_b[c0 + cc]; }
#pragma unroll
        for (int cc = 0; cc < OCHUNK; cc++) {
            float a = av[cc], b = bv[cc];
            float o8[8];
#pragma unroll
            for (int l = 0; l < 8; l++)
                o8[l] = fmaf(a, Ss[l], b) + xs[cc][l];
            stg_evict_first8(out + base + (size_t)cc * HW_, o8);
        }
        return;
    }

    // slow path (weight deviants exist)
    for (int cc = 0; cc < OCHUNK; cc++) {
        int c = c0 + cc;
        float a = g_a[c], b = g_b[c];
        float Sc[8];
#pragma unroll
        for (int l = 0; l < 8; l++) Sc[l] = Ss[l];
        int cnt = g_devCnt[c];
        if (cnt != 0) {
            const int* list = g_devList + c * KW_CAP;
            int h = hw / W_, w0 = hw - (hw / W_) * W_;
            for (int j = 0; j < cnt; j++) {
                int e = list[j];
                int cin = e >> 6;
                int k   = (e >> 2) & 15;
                float delta = (float)((e & 3) - 2);
                int dh = k / 3 - 1, dw = k % 3 - 1;
#pragma unroll
                for (int l = 0; l < 8; l++)
                    Sc[l] += delta * signx_at(x, n, cin, h + dh, w0 + l + dw);
            }
        }
        size_t idx = base + (size_t)cc * HW_;
#pragma unroll
        for (int l = 0; l < 8; l++)
            out[idx + l] = fmaf(a, Sc[l], b) + x[idx + l];
    }
}

// ---------------- launch -----------------------------------------------------
extern "C" void kernel_launch(void* const* d_in, const int* in_sizes, int n_in,
                              void* d_out, int out_size) {
    const float* x     = (const float*)d_in[0];
    const float* w     = (const float*)d_in[1];
    const float* gamma = (const float*)d_in[2];
    const float* beta  = (const float*)d_in[3];
    float* out = (float*)d_out;

    k_front<<<FRONT_G, 256>>>(x, w, gamma, beta);   // 648 blocks
    {
        dim3 grid(OUT_BLOCKS, C_ / OCHUNK);          // (49, 64), exact
        k_out<<<grid, 256>>>(x, out);
    }
}